// round 3
// baseline (speedup 1.0000x reference)
#include <cuda_runtime.h>

#define D_MODEL 1024
#define NHEAD   16
#define DK      64
#define BATCH   2
#define SEQ     2048
#define MTOT    (BATCH*SEQ)   // 4096

// ---------------- scratch (static device globals; no allocations) ----------
__device__ float g_Q[(size_t)BATCH*NHEAD*SEQ*DK];
__device__ float g_K[(size_t)BATCH*NHEAD*SEQ*DK];
__device__ float g_V[(size_t)BATCH*NHEAD*SEQ*DK];
__device__ float g_O[(size_t)MTOT*D_MODEL];

struct QKVArgs {
    const float* X[3];
    const float* W[3];
    const float* Bv[3];
};

// ---------------- shared GEMM mainloop: out[m,n] = sum_k X[m,k]*W[n,k] -----
// 128x128 block tile, BK=16, 256 threads, 8x8 micro-tile per thread.
__device__ __forceinline__ void gemm_mainloop(
    const float* __restrict__ X, const float* __restrict__ W,
    int m0, int n0, int tid, float acc[8][8],
    float (*As)[132], float (*Bs)[132])
{
    const int lrow = tid >> 2;            // 0..63
    const int lcol = (tid & 3) << 2;      // 0,4,8,12
    const int tx = tid & 15, ty = tid >> 4;

    for (int k0 = 0; k0 < D_MODEL; k0 += 16) {
        float4 a0 = *(const float4*)(X + (size_t)(m0 + lrow     ) * D_MODEL + k0 + lcol);
        float4 a1 = *(const float4*)(X + (size_t)(m0 + lrow + 64) * D_MODEL + k0 + lcol);
        float4 b0 = *(const float4*)(W + (size_t)(n0 + lrow     ) * D_MODEL + k0 + lcol);
        float4 b1 = *(const float4*)(W + (size_t)(n0 + lrow + 64) * D_MODEL + k0 + lcol);
        __syncthreads();
        As[lcol+0][lrow] = a0.x; As[lcol+1][lrow] = a0.y;
        As[lcol+2][lrow] = a0.z; As[lcol+3][lrow] = a0.w;
        As[lcol+0][lrow+64] = a1.x; As[lcol+1][lrow+64] = a1.y;
        As[lcol+2][lrow+64] = a1.z; As[lcol+3][lrow+64] = a1.w;
        Bs[lcol+0][lrow] = b0.x; Bs[lcol+1][lrow] = b0.y;
        Bs[lcol+2][lrow] = b0.z; Bs[lcol+3][lrow] = b0.w;
        Bs[lcol+0][lrow+64] = b1.x; Bs[lcol+1][lrow+64] = b1.y;
        Bs[lcol+2][lrow+64] = b1.z; Bs[lcol+3][lrow+64] = b1.w;
        __syncthreads();
        #pragma unroll
        for (int kk = 0; kk < 16; ++kk) {
            float am[8], bn[8];
            *(float4*)&am[0] = *(const float4*)&As[kk][ty*4];
            *(float4*)&am[4] = *(const float4*)&As[kk][64 + ty*4];
            *(float4*)&bn[0] = *(const float4*)&Bs[kk][tx*4];
            *(float4*)&bn[4] = *(const float4*)&Bs[kk][64 + tx*4];
            #pragma unroll
            for (int i = 0; i < 8; ++i)
                #pragma unroll
                for (int j = 0; j < 8; ++j)
                    acc[i][j] = fmaf(am[i], bn[j], acc[i][j]);
        }
    }
}

// ---------------- fused QKV projection: grid (8, 32, 3) --------------------
__global__ __launch_bounds__(256) void gemm_qkv_kernel(QKVArgs args) {
    __shared__ float As[16][132];
    __shared__ float Bs[16][132];
    const int z = blockIdx.z;
    const float* X    = args.X[z];
    const float* W    = args.W[z];
    const float* bias = args.Bv[z];
    float* outp = (z == 0) ? g_Q : (z == 1) ? g_K : g_V;

    const int m0 = blockIdx.y * 128;
    const int n0 = blockIdx.x * 128;
    const int tid = threadIdx.x;
    const int tx = tid & 15, ty = tid >> 4;

    float acc[8][8] = {};
    gemm_mainloop(X, W, m0, n0, tid, acc, As, Bs);

    float bv[8];
    #pragma unroll
    for (int j = 0; j < 4; ++j) {
        bv[j]     = bias[n0 +      tx*4 + j];
        bv[4 + j] = bias[n0 + 64 + tx*4 + j];
    }
    #pragma unroll
    for (int i = 0; i < 8; ++i) {
        int m = m0 + ty*4 + (i & 3) + ((i >= 4) ? 64 : 0);
        int bb = m >> 11;            // /SEQ
        int s  = m & (SEQ - 1);
        #pragma unroll
        for (int half = 0; half < 2; ++half) {
            int n = n0 + half*64 + tx*4;
            int h = n >> 6;
            int d = n & 63;
            float4 v;
            v.x = acc[i][half*4+0] + bv[half*4+0];
            v.y = acc[i][half*4+1] + bv[half*4+1];
            v.z = acc[i][half*4+2] + bv[half*4+2];
            v.w = acc[i][half*4+3] + bv[half*4+3];
            *(float4*)(outp + ((size_t)((bb*NHEAD + h)*SEQ + s)) * DK + d) = v;
        }
    }
}

// ---------------- output projection: grid (8, 32) --------------------------
__global__ __launch_bounds__(256) void gemm_out_kernel(
    const float* __restrict__ W, const float* __restrict__ bias,
    float* __restrict__ out)
{
    __shared__ float As[16][132];
    __shared__ float Bs[16][132];
    const int m0 = blockIdx.y * 128;
    const int n0 = blockIdx.x * 128;
    const int tid = threadIdx.x;
    const int tx = tid & 15, ty = tid >> 4;

    float acc[8][8] = {};
    gemm_mainloop(g_O, W, m0, n0, tid, acc, As, Bs);

    float bv[8];
    #pragma unroll
    for (int j = 0; j < 4; ++j) {
        bv[j]     = bias[n0 +      tx*4 + j];
        bv[4 + j] = bias[n0 + 64 + tx*4 + j];
    }
    #pragma unroll
    for (int i = 0; i < 8; ++i) {
        int m = m0 + ty*4 + (i & 3) + ((i >= 4) ? 64 : 0);
        #pragma unroll
        for (int half = 0; half < 2; ++half) {
            int n = n0 + half*64 + tx*4;
            float4 v;
            v.x = acc[i][half*4+0] + bv[half*4+0];
            v.y = acc[i][half*4+1] + bv[half*4+1];
            v.z = acc[i][half*4+2] + bv[half*4+2];
            v.w = acc[i][half*4+3] + bv[half*4+3];
            *(float4*)(out + (size_t)m * D_MODEL + n) = v;
        }
    }
}

// ---------------- flash attention: grid (32, 16, 2), 256 threads -----------
// Tiles: Br=64 queries x Bc=64 keys, d=64. Smem (exactly 48KB static):
//   Qt[d][r]  transposed+swizzled, pre-scaled by 1/sqrt(dk)
//   KPt       K transposed+swizzled, then reused for P transposed (Pt[j][r])
//   Vs[j][d]  natural
// Swizzle for transposed tiles: word = d*64 + 4*((r>>2) ^ (d>>2)) + (r&3).
__global__ __launch_bounds__(256) void attn_kernel() {
    __shared__ float Qt [64*64];
    __shared__ float KPt[64*64];
    __shared__ float Vs [64*64];

    const int qt = blockIdx.x;          // query tile
    const int h  = blockIdx.y;
    const int b  = blockIdx.z;
    const int tid = threadIdx.x;
    const int tx = tid & 15, ty = tid >> 4;

    const float* Qg = g_Q + ((size_t)(b*NHEAD + h)*SEQ + qt*64) * DK;
    const float* Kg = g_K + ((size_t)(b*NHEAD + h)*SEQ) * DK;
    const float* Vg = g_V + ((size_t)(b*NHEAD + h)*SEQ) * DK;

    const float SCALE = 0.125f;  // 1/sqrt(64)

    // load Q tile, transposed + scaled
    #pragma unroll
    for (int it = 0; it < 4; ++it) {
        int idx = tid + it*256;
        int r  = idx >> 4;
        int cc = idx & 15;
        float4 v = *(const float4*)(Qg + (size_t)r*DK + cc*4);
        int base = 4*((r >> 2) ^ cc) + (r & 3);
        int d0 = cc*4;
        Qt[(d0+0)*64 + base] = v.x * SCALE;
        Qt[(d0+1)*64 + base] = v.y * SCALE;
        Qt[(d0+2)*64 + base] = v.z * SCALE;
        Qt[(d0+3)*64 + base] = v.w * SCALE;
    }

    float m_i[4], l_i[4], o[4][4];
    #pragma unroll
    for (int i = 0; i < 4; ++i) {
        m_i[i] = -1e30f; l_i[i] = 0.f;
        #pragma unroll
        for (int u = 0; u < 4; ++u) o[i][u] = 0.f;
    }

    for (int t = 0; t < SEQ/64; ++t) {
        // load K (transposed+swizzled) and V (natural)
        #pragma unroll
        for (int it = 0; it < 4; ++it) {
            int idx = tid + it*256;
            int r  = idx >> 4;
            int cc = idx & 15;
            const float* kp = Kg + (size_t)(t*64 + r)*DK + cc*4;
            const float* vp = Vg + (size_t)(t*64 + r)*DK + cc*4;
            float4 kv = *(const float4*)kp;
            float4 vv = *(const float4*)vp;
            int base = 4*((r >> 2) ^ cc) + (r & 3);
            int d0 = cc*4;
            KPt[(d0+0)*64 + base] = kv.x;
            KPt[(d0+1)*64 + base] = kv.y;
            KPt[(d0+2)*64 + base] = kv.z;
            KPt[(d0+3)*64 + base] = kv.w;
            *(float4*)(Vs + r*64 + d0) = vv;
        }
        __syncthreads();

        // S = (Q*scale) K^T   [4x4 per thread]
        float s[4][4] = {};
        #pragma unroll 8
        for (int d = 0; d < 64; ++d) {
            float4 qa = *(const float4*)(Qt  + d*64 + 4*(ty ^ (d >> 2)));
            float4 kb = *(const float4*)(KPt + d*64 + 4*(tx ^ (d >> 2)));
            float qr[4] = {qa.x, qa.y, qa.z, qa.w};
            float kr[4] = {kb.x, kb.y, kb.z, kb.w};
            #pragma unroll
            for (int i = 0; i < 4; ++i)
                #pragma unroll
                for (int u = 0; u < 4; ++u)
                    s[i][u] = fmaf(qr[i], kr[u], s[i][u]);
        }

        // online softmax (row reductions across tx via shfl_xor, bits 0..3)
        #pragma unroll
        for (int i = 0; i < 4; ++i) {
            float mx = fmaxf(fmaxf(s[i][0], s[i][1]), fmaxf(s[i][2], s[i][3]));
            mx = fmaxf(mx, __shfl_xor_sync(0xffffffffu, mx, 1));
            mx = fmaxf(mx, __shfl_xor_sync(0xffffffffu, mx, 2));
            mx = fmaxf(mx, __shfl_xor_sync(0xffffffffu, mx, 4));
            mx = fmaxf(mx, __shfl_xor_sync(0xffffffffu, mx, 8));
            float mnew  = fmaxf(m_i[i], mx);
            float alpha = __expf(m_i[i] - mnew);
            float rs = 0.f;
            #pragma unroll
            for (int u = 0; u < 4; ++u) {
                float p = __expf(s[i][u] - mnew);
                s[i][u] = p;
                rs += p;
            }
            rs += __shfl_xor_sync(0xffffffffu, rs, 1);
            rs += __shfl_xor_sync(0xffffffffu, rs, 2);
            rs += __shfl_xor_sync(0xffffffffu, rs, 4);
            rs += __shfl_xor_sync(0xffffffffu, rs, 8);
            l_i[i] = l_i[i] * alpha + rs;
            m_i[i] = mnew;
            #pragma unroll
            for (int u = 0; u < 4; ++u) o[i][u] *= alpha;
        }
        __syncthreads();   // everyone done reading K before P overwrites it

        // write P transposed into KPt: Pt[j][r], j = 4*tx+u, r = 4*ty+i
        #pragma unroll
        for (int u = 0; u < 4; ++u) {
            int j = 4*tx + u;
            float4 pv = make_float4(s[0][u], s[1][u], s[2][u], s[3][u]);
            *(float4*)(KPt + j*64 + 4*(ty ^ tx)) = pv;
        }
        __syncthreads();

        // O += P @ V
        #pragma unroll 8
        for (int j = 0; j < 64; ++j) {
            float4 pa = *(const float4*)(KPt + j*64 + 4*(ty ^ (j >> 2)));
            float4 vb = *(const float4*)(Vs  + j*64 + 4*tx);
            float pr[4] = {pa.x, pa.y, pa.z, pa.w};
            float vr[4] = {vb.x, vb.y, vb.z, vb.w};
            #pragma unroll
            for (int i = 0; i < 4; ++i)
                #pragma unroll
                for (int u = 0; u < 4; ++u)
                    o[i][u] = fmaf(pr[i], vr[u], o[i][u]);
        }
        __syncthreads();   // before next tile overwrites KPt / Vs
    }

    // epilogue: O[b][s][h*64 + d] into [B, S, D_MODEL]
    float* Og = g_O + ((size_t)b*SEQ + qt*64) * D_MODEL + h*DK;
    #pragma unroll
    for (int i = 0; i < 4; ++i) {
        float inv = 1.0f / l_i[i];
        int r = 4*ty + i;
        float4 v = make_float4(o[i][0]*inv, o[i][1]*inv, o[i][2]*inv, o[i][3]*inv);
        *(float4*)(Og + (size_t)r*D_MODEL + 4*tx) = v;
    }
}

// ---------------- launcher --------------------------------------------------
extern "C" void kernel_launch(void* const* d_in, const int* in_sizes, int n_in,
                              void* d_out, int out_size) {
    const float* query = (const float*)d_in[0];
    const float* key   = (const float*)d_in[1];
    const float* value = (const float*)d_in[2];
    const float* Wq    = (const float*)d_in[3];
    const float* bq    = (const float*)d_in[4];
    const float* Wk    = (const float*)d_in[5];
    const float* bk    = (const float*)d_in[6];
    const float* Wv    = (const float*)d_in[7];
    const float* bv    = (const float*)d_in[8];
    const float* Wo    = (const float*)d_in[9];
    const float* bo    = (const float*)d_in[10];
    float* out = (float*)d_out;

    QKVArgs args;
    args.X[0] = query; args.X[1] = key; args.X[2] = value;
    args.W[0] = Wq;    args.W[1] = Wk;  args.W[2] = Wv;
    args.Bv[0] = bq;   args.Bv[1] = bk; args.Bv[2] = bv;

    dim3 gQKV(D_MODEL/128, MTOT/128, 3);   // (8, 32, 3)
    gemm_qkv_kernel<<<gQKV, 256>>>(args);

    dim3 gAtt(SEQ/64, NHEAD, BATCH);       // (32, 16, 2)
    attn_kernel<<<gAtt, 256>>>();

    dim3 gOut(D_MODEL/128, MTOT/128, 1);   // (8, 32)
    gemm_out_kernel<<<gOut, 256>>>(Wo, bo, out);
}